// round 1
// baseline (speedup 1.0000x reference)
#include <cuda_runtime.h>
#include <cuda_bf16.h>
#include <cstdint>

// Problem dims (fixed by the dataset)
#define HD    4096
#define MDIM  11008
#define TOK   512
#define NBLK  64        // NF4 quant blocksize

#define BT 128
#define BM 128
#define BK 32
#define SPAD 4          // smem row stride = BK+SPAD = 36 -> conflict-free frag loads

__constant__ float NF4c[16] = {
    -1.0f, -0.6961928009986877f, -0.5250730514526367f, -0.39491748809814453f,
    -0.28444138169288635f, -0.18477343022823334f, -0.09105003625154495f, 0.0f,
    0.07958029955625534f, 0.16093020141124725f, 0.24611230194568634f,
    0.33791524171829224f, 0.44070982933044434f, 0.5626170039176941f,
    0.7229568362236023f, 1.0f};

// Scratch (static device allocations are the sanctioned workaround)
__device__ unsigned char g_codes_gate[(size_t)MDIM * HD];
__device__ unsigned char g_codes_up[(size_t)MDIM * HD];
__device__ unsigned char g_codes_down[(size_t)HD * MDIM];
__device__ float g_g[(size_t)TOK * MDIM];
__device__ float g_u[(size_t)TOK * MDIM];
__device__ float g_h[(size_t)TOK * MDIM];

__device__ __forceinline__ float tf32r(float x) {
    uint32_t u;
    asm("cvt.rna.tf32.f32 %0, %1;" : "=r"(u) : "f"(x));
    return __uint_as_float(u);
}

// ---------------- pack int32 codes -> uint8 ----------------
__global__ void pack_codes(const int* __restrict__ src, unsigned char* __restrict__ dst, int n4) {
    int i = blockIdx.x * blockDim.x + threadIdx.x;
    if (i < n4) {
        int4 v = ((const int4*)src)[i];
        uchar4 o;
        o.x = (unsigned char)v.x; o.y = (unsigned char)v.y;
        o.z = (unsigned char)v.z; o.w = (unsigned char)v.w;
        ((uchar4*)dst)[i] = o;
    }
}

// ---------------- fused dequant TF32 GEMM ----------------
// out[T x Mout] = A[T x K] @ dequant(codes[Mout x K])^T
__global__ __launch_bounds__(256, 2) void gemm_dequant(
    const float* __restrict__ A,
    const unsigned char* __restrict__ codes,
    const float* __restrict__ absmax,
    float* __restrict__ out,
    int K, int Mout)
{
    __shared__ float As[BT][BK + SPAD];
    __shared__ float Ws[BM][BK + SPAD];

    const int tid = threadIdx.x;
    const int warp = tid >> 5, lane = tid & 31;
    const int warpT = warp >> 2, warpM = warp & 3;     // 2 x 4 warps
    const int t0 = blockIdx.y * BT;
    const int m0 = blockIdx.x * BM;
    const int kb = K >> 6;                              // absmax blocks per row

    const int frow = tid >> 3;   // 0..31
    const int fc = tid & 7;      // 0..7

    float acc[4][4][4];
#pragma unroll
    for (int i = 0; i < 4; i++)
#pragma unroll
        for (int j = 0; j < 4; j++)
#pragma unroll
            for (int r = 0; r < 4; r++) acc[i][j][r] = 0.f;

    const int tg = lane >> 2, tig = lane & 3;

    for (int k0 = 0; k0 < K; k0 += BK) {
        // fill A tile (tf32-rounded)
#pragma unroll
        for (int r = 0; r < BT; r += 32) {
            int row = frow + r;
            float4 v = *(const float4*)(&A[(size_t)(t0 + row) * K + k0 + fc * 4]);
            As[row][fc * 4 + 0] = tf32r(v.x);
            As[row][fc * 4 + 1] = tf32r(v.y);
            As[row][fc * 4 + 2] = tf32r(v.z);
            As[row][fc * 4 + 3] = tf32r(v.w);
        }
        // fill W tile: dequant NF4 * absmax, tf32-rounded
#pragma unroll
        for (int r = 0; r < BM; r += 32) {
            int row = frow + r;
            int m = m0 + row;
            float am = absmax[(size_t)m * kb + (k0 >> 6)];
            uchar4 c = *(const uchar4*)(&codes[(size_t)m * K + k0 + fc * 4]);
            Ws[row][fc * 4 + 0] = tf32r(NF4c[c.x] * am);
            Ws[row][fc * 4 + 1] = tf32r(NF4c[c.y] * am);
            Ws[row][fc * 4 + 2] = tf32r(NF4c[c.z] * am);
            Ws[row][fc * 4 + 3] = tf32r(NF4c[c.w] * am);
        }
        __syncthreads();

#pragma unroll
        for (int ks = 0; ks < BK; ks += 8) {
            uint32_t a[4][4], b[4][2];
#pragma unroll
            for (int i = 0; i < 4; i++) {
                int tr = warpT * 64 + i * 16;
                a[i][0] = __float_as_uint(As[tr + tg][ks + tig]);
                a[i][1] = __float_as_uint(As[tr + tg + 8][ks + tig]);
                a[i][2] = __float_as_uint(As[tr + tg][ks + tig + 4]);
                a[i][3] = __float_as_uint(As[tr + tg + 8][ks + tig + 4]);
            }
#pragma unroll
            for (int j = 0; j < 4; j++) {
                int mr = warpM * 32 + j * 8;
                b[j][0] = __float_as_uint(Ws[mr + tg][ks + tig]);
                b[j][1] = __float_as_uint(Ws[mr + tg][ks + tig + 4]);
            }
#pragma unroll
            for (int i = 0; i < 4; i++)
#pragma unroll
                for (int j = 0; j < 4; j++) {
                    asm volatile(
                        "mma.sync.aligned.m16n8k8.row.col.f32.tf32.tf32.f32 "
                        "{%0,%1,%2,%3}, {%4,%5,%6,%7}, {%8,%9}, {%0,%1,%2,%3};"
                        : "+f"(acc[i][j][0]), "+f"(acc[i][j][1]),
                          "+f"(acc[i][j][2]), "+f"(acc[i][j][3])
                        : "r"(a[i][0]), "r"(a[i][1]), "r"(a[i][2]), "r"(a[i][3]),
                          "r"(b[j][0]), "r"(b[j][1]));
                }
        }
        __syncthreads();
    }

    // epilogue
#pragma unroll
    for (int i = 0; i < 4; i++) {
#pragma unroll
        for (int j = 0; j < 4; j++) {
            int t = t0 + warpT * 64 + i * 16 + tg;
            int m = m0 + warpM * 32 + j * 8 + tig * 2;
            float2 lo = make_float2(acc[i][j][0], acc[i][j][1]);
            float2 hi = make_float2(acc[i][j][2], acc[i][j][3]);
            *(float2*)(&out[(size_t)t * Mout + m]) = lo;
            *(float2*)(&out[(size_t)(t + 8) * Mout + m]) = hi;
        }
    }
}

// ---------------- silu(g) * u ----------------
__global__ void silu_mul(const float* __restrict__ g, const float* __restrict__ u,
                         float* __restrict__ h, int n4) {
    int i = blockIdx.x * blockDim.x + threadIdx.x;
    if (i < n4) {
        float4 gv = ((const float4*)g)[i];
        float4 uv = ((const float4*)u)[i];
        float4 o;
        o.x = gv.x / (1.f + expf(-gv.x)) * uv.x;
        o.y = gv.y / (1.f + expf(-gv.y)) * uv.y;
        o.z = gv.z / (1.f + expf(-gv.z)) * uv.z;
        o.w = gv.w / (1.f + expf(-gv.w)) * uv.w;
        ((float4*)h)[i] = o;
    }
}

extern "C" void kernel_launch(void* const* d_in, const int* in_sizes, int n_in,
                              void* d_out, int out_size) {
    (void)in_sizes; (void)n_in; (void)out_size;
    const float* x           = (const float*)d_in[0];
    const int*   gate_codes  = (const int*)d_in[1];
    const float* gate_absmax = (const float*)d_in[2];
    const int*   up_codes    = (const int*)d_in[3];
    const float* up_absmax   = (const float*)d_in[4];
    const int*   down_codes  = (const int*)d_in[5];
    const float* down_absmax = (const float*)d_in[6];
    float* out = (float*)d_out;

    unsigned char *cg, *cu, *cd;
    float *gg, *gu, *gh;
    cudaGetSymbolAddress((void**)&cg, g_codes_gate);
    cudaGetSymbolAddress((void**)&cu, g_codes_up);
    cudaGetSymbolAddress((void**)&cd, g_codes_down);
    cudaGetSymbolAddress((void**)&gg, g_g);
    cudaGetSymbolAddress((void**)&gu, g_u);
    cudaGetSymbolAddress((void**)&gh, g_h);

    const int ncodes = MDIM * HD;           // 45,088,768
    const int n4 = ncodes / 4;              // 11,272,192
    pack_codes<<<(n4 + 255) / 256, 256>>>(gate_codes, cg, n4);
    pack_codes<<<(n4 + 255) / 256, 256>>>(up_codes, cu, n4);
    pack_codes<<<(n4 + 255) / 256, 256>>>(down_codes, cd, n4);

    dim3 grid1(MDIM / BM, TOK / BT);        // (86, 4)
    gemm_dequant<<<grid1, 256>>>(x, cg, gate_absmax, gg, HD, MDIM);
    gemm_dequant<<<grid1, 256>>>(x, cu, up_absmax, gu, HD, MDIM);

    const int nh4 = (TOK * MDIM) / 4;       // 1,409,024
    silu_mul<<<(nh4 + 255) / 256, 256>>>(gg, gu, gh, nh4);

    dim3 grid2(HD / BM, TOK / BT);          // (32, 4)
    gemm_dequant<<<grid2, 256>>>(gh, cd, down_absmax, out, MDIM, HD);
}

// round 2
// speedup vs baseline: 2.4127x; 2.4127x over previous
#include <cuda_runtime.h>
#include <cuda_bf16.h>
#include <cstdint>

// Problem dims (fixed by dataset)
#define HD    4096
#define MDIM  11008
#define TOK   512

__constant__ float NF4c[16] = {
    -1.0f, -0.6961928009986877f, -0.5250730514526367f, -0.39491748809814453f,
    -0.28444138169288635f, -0.18477343022823334f, -0.09105003625154495f, 0.0f,
    0.07958029955625534f, 0.16093020141124725f, 0.24611230194568634f,
    0.33791524171829224f, 0.44070982933044434f, 0.5626170039176941f,
    0.7229568362236023f, 1.0f};

// Static device scratch (sanctioned workaround for no-alloc rule)
__device__ unsigned char g_codes_gate[(size_t)MDIM * HD];
__device__ unsigned char g_codes_up[(size_t)MDIM * HD];
__device__ unsigned char g_codes_down[(size_t)HD * MDIM];
__device__ float g_xp[(size_t)TOK * HD];      // x in permuted fragment layout (tf32-rounded)
__device__ float g_g[(size_t)TOK * MDIM];     // gate output, linear
__device__ float g_hp[(size_t)TOK * MDIM];    // h = silu(g)*u, permuted layout (tf32-rounded)

__device__ __forceinline__ float tf32r(float x) {
    uint32_t u;
    asm("cvt.rna.tf32.f32 %0, %1;" : "=r"(u) : "f"(x));
    return __uint_as_float(u);
}

__device__ __forceinline__ void cpa16(void* dst, const void* src) {
    uint32_t d = (uint32_t)__cvta_generic_to_shared(dst);
    asm volatile("cp.async.cg.shared.global [%0], [%1], 16;" :: "r"(d), "l"(src));
}
__device__ __forceinline__ void cpa4(void* dst, const void* src) {
    uint32_t d = (uint32_t)__cvta_generic_to_shared(dst);
    asm volatile("cp.async.ca.shared.global [%0], [%1], 4;" :: "r"(d), "l"(src));
}

// ---------------- pack int32 codes -> uint8 ----------------
__global__ void pack_codes(const int* __restrict__ src, unsigned char* __restrict__ dst, int n4) {
    int i = blockIdx.x * blockDim.x + threadIdx.x;
    if (i < n4) {
        int4 v = ((const int4*)src)[i];
        uchar4 o;
        o.x = (unsigned char)v.x; o.y = (unsigned char)v.y;
        o.z = (unsigned char)v.z; o.w = (unsigned char)v.w;
        ((uchar4*)dst)[i] = o;
    }
}

// ---------------- permute x -> fragment-register layout ----------------
// layout: [T/16][K/8][32][4]; lane=(r%8)*4+(c%4); v = (r/8) + 2*(c/4)
// a-fragment order: v0=(r,c) v1=(r+8,c) v2=(r,c+4) v3=(r+8,c+4)
__global__ void permute_x(const float* __restrict__ X, float* __restrict__ Xp, int T, int K) {
    int gw = (blockIdx.x * blockDim.x + threadIdx.x) >> 5;
    int lane = threadIdx.x & 31;
    int nkb = K >> 3;
    int nblocks = (T >> 4) * nkb;
    if (gw >= nblocks) return;
    int tb = gw / nkb, kb = gw % nkb;
    int r = lane >> 2, c = lane & 3;
    const float* base = X + (size_t)(tb * 16 + r) * K + kb * 8 + c;
    float4 v;
    v.x = tf32r(base[0]);
    v.y = tf32r(base[(size_t)8 * K]);
    v.z = tf32r(base[4]);
    v.w = tf32r(base[(size_t)8 * K + 4]);
    ((float4*)(Xp + ((size_t)gw * 32 + lane) * 4))[0] = v;
}

// ---------------- fused dequant TF32 GEMM ----------------
// out[T x Mout] = Aperm[T x K] @ dequant(codes[Mout x K])^T
// EPI 0: linear fp32 store.  EPI 1: read g, h=silu(g)*acc, store h to perm layout.
// BT = TI*32 (TI a-tiles of 16 rows per warpT-half), BM=128, BK=32, 3-stage cp.async.
template<int TI, int EPI>
__global__ __launch_bounds__(256, 2) void gemm_nf4(
    const float* __restrict__ Ap,
    const unsigned char* __restrict__ codes,
    const float* __restrict__ absmax,
    const float* __restrict__ gbuf,
    float* __restrict__ out,
    int K, int Mout)
{
    extern __shared__ char smem[];
    constexpr int ASTG = TI * 2 * 4 * 128;        // floats per A stage
    float* As = (float*)smem;
    unsigned char* Cs = (unsigned char*)(As + 3 * ASTG);  // 3 x 128 x 48 bytes
    float* Ams = (float*)(Cs + 3 * 128 * 48);             // 3 x 128
    float* Lut = Ams + 3 * 128;                           // 16 x 32 replicated

    const int tid = threadIdx.x;
    const int warp = tid >> 5, lane = tid & 31;
    const int warpT = warp >> 2, warpM = warp & 3;
    const int tg = lane >> 2, tig = lane & 3;
    const int t0 = blockIdx.y * (TI * 32);
    const int m0 = blockIdx.x * 128;
    const int t0g = t0 >> 4;
    const int kb = K >> 6;
    const int K8 = K >> 3;
    const unsigned sh = tig * 8;

    for (int i = tid; i < 512; i += 256) Lut[i] = NF4c[i >> 5];

    float acc[TI][4][4];
#pragma unroll
    for (int i = 0; i < TI; i++)
#pragma unroll
        for (int j = 0; j < 4; j++)
#pragma unroll
            for (int r = 0; r < 4; r++) acc[i][j][r] = 0.f;

    auto load_stage = [&](int s, int k0) {
        float* AsS = As + s * ASTG;
        unsigned char* CsS = Cs + s * 128 * 48;
        float* AmS = Ams + s * 128;
#pragma unroll
        for (int it = 0; it < TI; it++) {
            int idx = tid + it * 256;
            int tt = idx >> 7, c = idx & 127;
            const float* src = Ap + ((size_t)(t0g + tt) * K8 + (k0 >> 3)) * 128 + c * 4;
            cpa16(AsS + tt * 512 + c * 4, src);
        }
        {
            int row = tid >> 1, ch = tid & 1;
            const unsigned char* src = codes + (size_t)(m0 + row) * K + k0 + ch * 16;
            cpa16(CsS + row * 48 + ch * 16, src);
        }
        if (tid < 128)
            cpa4(AmS + tid, absmax + (size_t)(m0 + tid) * kb + (k0 >> 6));
        asm volatile("cp.async.commit_group;" ::: "memory");
    };

    const int ktiles = K >> 5;
    load_stage(0, 0);
    load_stage(1, 32);

    int s = 0;
    for (int kt = 0; kt < ktiles; kt++) {
        if (kt < ktiles - 1) asm volatile("cp.async.wait_group 1;" ::: "memory");
        else                 asm volatile("cp.async.wait_group 0;" ::: "memory");
        __syncthreads();

        const float* AsS = As + s * ASTG;
        const unsigned char* CsS = Cs + s * 128 * 48;
        const float* AmS = Ams + s * 128;

        float am[4];
#pragma unroll
        for (int j = 0; j < 4; j++) am[j] = AmS[warpM * 32 + j * 8 + tg];

#pragma unroll
        for (int kc = 0; kc < 4; kc++) {
            const int ks = kc * 8;
            uint32_t a[TI][4], b[4][2];
#pragma unroll
            for (int i = 0; i < TI; i++) {
                int tt = warpT * TI + i;
                float4 v = *(const float4*)(AsS + ((tt * 4 + kc) * 32 + lane) * 4);
                a[i][0] = __float_as_uint(v.x);
                a[i][1] = __float_as_uint(v.y);
                a[i][2] = __float_as_uint(v.z);
                a[i][3] = __float_as_uint(v.w);
            }
#pragma unroll
            for (int j = 0; j < 4; j++) {
                int mr = warpM * 32 + j * 8 + tg;
                uint2 w = *(const uint2*)(CsS + mr * 48 + ks);
                int c0 = (w.x >> sh) & 0xFF;
                int c1 = (w.y >> sh) & 0xFF;
                b[j][0] = __float_as_uint(tf32r(Lut[(c0 << 5) + lane] * am[j]));
                b[j][1] = __float_as_uint(tf32r(Lut[(c1 << 5) + lane] * am[j]));
            }
#pragma unroll
            for (int i = 0; i < TI; i++)
#pragma unroll
                for (int j = 0; j < 4; j++) {
                    asm volatile(
                        "mma.sync.aligned.m16n8k8.row.col.f32.tf32.tf32.f32 "
                        "{%0,%1,%2,%3}, {%4,%5,%6,%7}, {%8,%9}, {%0,%1,%2,%3};"
                        : "+f"(acc[i][j][0]), "+f"(acc[i][j][1]),
                          "+f"(acc[i][j][2]), "+f"(acc[i][j][3])
                        : "r"(a[i][0]), "r"(a[i][1]), "r"(a[i][2]), "r"(a[i][3]),
                          "r"(b[j][0]), "r"(b[j][1]));
                }
        }

        int kn = kt + 2;
        if (kn < ktiles) load_stage((s + 2) % 3, kn * 32);
        s++; if (s == 3) s = 0;
    }

    if (EPI == 1) {
        // h = silu(g) * acc, tf32-rounded, stored to perm layout via smem stage
        __syncthreads();
        float* Ep = (float*)smem;   // [TI*2][16][32][4] = TI*2*2048 floats
#pragma unroll
        for (int i = 0; i < TI; i++) {
#pragma unroll
            for (int j = 0; j < 4; j++) {
                int t = t0 + warpT * (TI * 16) + i * 16 + tg;
                int m = m0 + warpM * 32 + j * 8 + tig * 2;
                float2 glo = *(const float2*)&gbuf[(size_t)t * Mout + m];
                float2 ghi = *(const float2*)&gbuf[(size_t)(t + 8) * Mout + m];
                float h00 = glo.x / (1.f + __expf(-glo.x)) * acc[i][j][0];
                float h01 = glo.y / (1.f + __expf(-glo.y)) * acc[i][j][1];
                float h10 = ghi.x / (1.f + __expf(-ghi.x)) * acc[i][j][2];
                float h11 = ghi.y / (1.f + __expf(-ghi.y)) * acc[i][j][3];
                int tt = warpT * TI + i;
                int mcl = warpM * 4 + j;
                float* blk = Ep + (tt * 16 + mcl) * 128;
                int ml = tig * 2;
                int l0 = tg * 4 + (ml & 3);
                int l1 = tg * 4 + ((ml + 1) & 3);
                int vh = (ml >> 2) * 2;
                blk[l0 * 4 + vh + 0] = tf32r(h00);
                blk[l1 * 4 + vh + 0] = tf32r(h01);
                blk[l0 * 4 + vh + 1] = tf32r(h10);
                blk[l1 * 4 + vh + 1] = tf32r(h11);
            }
        }
        __syncthreads();
        const int totchunks = TI * 2 * 512;   // 16B chunks
        for (int idx = tid; idx < totchunks; idx += 256) {
            int tt = idx >> 9, c2 = idx & 511;
            float4 v = *(const float4*)(Ep + tt * 2048 + c2 * 4);
            *(float4*)(out + ((size_t)(t0g + tt) * (Mout >> 3) + (m0 >> 3)) * 128 + c2 * 4) = v;
        }
    } else {
#pragma unroll
        for (int i = 0; i < TI; i++) {
#pragma unroll
            for (int j = 0; j < 4; j++) {
                int t = t0 + warpT * (TI * 16) + i * 16 + tg;
                int m = m0 + warpM * 32 + j * 8 + tig * 2;
                *(float2*)&out[(size_t)t * Mout + m] = make_float2(acc[i][j][0], acc[i][j][1]);
                *(float2*)&out[(size_t)(t + 8) * Mout + m] = make_float2(acc[i][j][2], acc[i][j][3]);
            }
        }
    }
}

extern "C" void kernel_launch(void* const* d_in, const int* in_sizes, int n_in,
                              void* d_out, int out_size) {
    (void)in_sizes; (void)n_in; (void)out_size;
    const float* x           = (const float*)d_in[0];
    const int*   gate_codes  = (const int*)d_in[1];
    const float* gate_absmax = (const float*)d_in[2];
    const int*   up_codes    = (const int*)d_in[3];
    const float* up_absmax   = (const float*)d_in[4];
    const int*   down_codes  = (const int*)d_in[5];
    const float* down_absmax = (const float*)d_in[6];
    float* out = (float*)d_out;

    unsigned char *cg, *cu, *cd;
    float *xp, *gg, *hp;
    cudaGetSymbolAddress((void**)&cg, g_codes_gate);
    cudaGetSymbolAddress((void**)&cu, g_codes_up);
    cudaGetSymbolAddress((void**)&cd, g_codes_down);
    cudaGetSymbolAddress((void**)&xp, g_xp);
    cudaGetSymbolAddress((void**)&gg, g_g);
    cudaGetSymbolAddress((void**)&hp, g_hp);

    // smem sizes
    const int SM_BIG = 3 * (4 * 2 * 4 * 128) * 4 + 3 * 128 * 48 + 3 * 128 * 4 + 512 * 4; // TI=4
    const int SM_SML = 3 * (2 * 2 * 4 * 128) * 4 + 3 * 128 * 48 + 3 * 128 * 4 + 512 * 4; // TI=2
    cudaFuncSetAttribute((const void*)gemm_nf4<4, 0>, cudaFuncAttributeMaxDynamicSharedMemorySize, SM_BIG);
    cudaFuncSetAttribute((const void*)gemm_nf4<4, 1>, cudaFuncAttributeMaxDynamicSharedMemorySize, SM_BIG);
    cudaFuncSetAttribute((const void*)gemm_nf4<2, 0>, cudaFuncAttributeMaxDynamicSharedMemorySize, SM_SML);

    const int ncodes = MDIM * HD;
    const int n4 = ncodes / 4;
    pack_codes<<<(n4 + 255) / 256, 256>>>(gate_codes, cg, n4);
    pack_codes<<<(n4 + 255) / 256, 256>>>(up_codes, cu, n4);
    pack_codes<<<(n4 + 255) / 256, 256>>>(down_codes, cd, n4);

    {
        int nwarps = (TOK / 16) * (HD / 8);
        int nthreads = nwarps * 32;
        permute_x<<<(nthreads + 255) / 256, 256>>>(x, xp, TOK, HD);
    }

    dim3 grid1(MDIM / 128, TOK / 128);   // (86, 4)
    gemm_nf4<4, 0><<<grid1, 256, SM_BIG>>>(xp, cg, gate_absmax, nullptr, gg, HD, MDIM);
    gemm_nf4<4, 1><<<grid1, 256, SM_BIG>>>(xp, cu, up_absmax, gg, hp, HD, MDIM);

    dim3 grid2(HD / 128, TOK / 64);      // (32, 8)
    gemm_nf4<2, 0><<<grid2, 256, SM_SML>>>(hp, cd, down_absmax, nullptr, out, MDIM, HD);
}

// round 4
// speedup vs baseline: 3.3544x; 1.3903x over previous
#include <cuda_runtime.h>
#include <cuda_fp16.h>
#include <cstdint>

// Problem dims (fixed by dataset)
#define HD    4096
#define MDIM  11008
#define TOK   512

__constant__ float NF4c[16] = {
    -1.0f, -0.6961928009986877f, -0.5250730514526367f, -0.39491748809814453f,
    -0.28444138169288635f, -0.18477343022823334f, -0.09105003625154495f, 0.0f,
    0.07958029955625534f, 0.16093020141124725f, 0.24611230194568634f,
    0.33791524171829224f, 0.44070982933044434f, 0.5626170039176941f,
    0.7229568362236023f, 1.0f};

// Static device scratch
__device__ unsigned char g_codes_gate[(size_t)MDIM * HD];
__device__ unsigned char g_codes_up[(size_t)MDIM * HD];
__device__ unsigned char g_codes_down[(size_t)HD * MDIM];
__device__ __half g_xq[(size_t)TOK * HD];    // x fp16, A-fragment permuted layout
__device__ float  g_g[(size_t)TOK * MDIM];   // gate GEMM out, linear fp32
__device__ __half g_hp[(size_t)TOK * MDIM];  // h = silu(g)*u, fp16 permuted layout

__device__ __forceinline__ void cpa16(uint32_t dst, const void* src) {
    asm volatile("cp.async.cg.shared.global [%0], [%1], 16;" :: "r"(dst), "l"(src));
}
__device__ __forceinline__ void cpa4(uint32_t dst, const void* src) {
    asm volatile("cp.async.ca.shared.global [%0], [%1], 4;" :: "r"(dst), "l"(src));
}
__device__ __forceinline__ uint32_t smem_u32(const void* p) {
    uint32_t a;
    asm("{ .reg .u64 t; cvta.to.shared.u64 t, %1; cvt.u32.u64 %0, t; }" : "=r"(a) : "l"(p));
    return a;
}
__device__ __forceinline__ uint32_t f2h2(float lo, float hi) {
    uint32_t r;
    asm("cvt.rn.f16x2.f32 %0, %2, %1;" : "=r"(r) : "f"(lo), "f"(hi));
    return r;
}

// ---------------- pack int32 codes -> uint8 ----------------
__global__ void pack_codes(const int* __restrict__ src, unsigned char* __restrict__ dst, int n4) {
    int i = blockIdx.x * blockDim.x + threadIdx.x;
    if (i < n4) {
        int4 v = ((const int4*)src)[i];
        uchar4 o;
        o.x = (unsigned char)v.x; o.y = (unsigned char)v.y;
        o.z = (unsigned char)v.z; o.w = (unsigned char)v.w;
        ((uchar4*)dst)[i] = o;
    }
}

// ---------------- permute x -> fp16 A-fragment layout ----------------
// layout: [T/16][K/16][32 lanes][4 x f16x2]; lane: tg=lane>>2 (row), tig=lane&3
// regs: a0=(tg, 2tig..+1)  a1=(tg+8, same)  a2=(tg, 2tig+8..)  a3=(tg+8, same)
__global__ void permute_xh(const float* __restrict__ X, __half* __restrict__ Xp, int T, int K) {
    int gw = (blockIdx.x * blockDim.x + threadIdx.x) >> 5;
    int lane = threadIdx.x & 31;
    int kb16 = K >> 4;
    if (gw >= (T >> 4) * kb16) return;
    int tb = gw / kb16, kb = gw % kb16;
    int tg = lane >> 2, tig = lane & 3;
    const float* p0 = X + (size_t)(tb * 16 + tg) * K + kb * 16 + tig * 2;
    const float* p1 = p0 + (size_t)8 * K;
    float2 v00 = *(const float2*)p0;
    float2 v10 = *(const float2*)p1;
    float2 v01 = *(const float2*)(p0 + 8);
    float2 v11 = *(const float2*)(p1 + 8);
    uint4 o;
    o.x = f2h2(v00.x, v00.y);
    o.y = f2h2(v10.x, v10.y);
    o.z = f2h2(v01.x, v01.y);
    o.w = f2h2(v11.x, v11.y);
    *(uint4*)(Xp + ((size_t)gw * 32 + lane) * 8) = o;
}

// ---------------- fused NF4-dequant fp16 HMMA GEMM ----------------
// out[T x Mout] = A[T x K] @ dequant(codes[Mout x K])^T
// BT = TI*32 tokens, BM = 128, BK = 32, 3-stage cp.async.
// EPI 0: linear fp32 store. EPI 1: h = silu(g)*acc -> fp16 permuted layout.
template<int TI, int EPI>
__global__ __launch_bounds__(256, 2) void gemm_h(
    const __half* __restrict__ Ap,
    const unsigned char* __restrict__ codes,
    const float* __restrict__ absmax,
    const float* __restrict__ gbuf,
    float* __restrict__ outf,
    __half* __restrict__ outh,
    int K, int Mout)
{
    constexpr int A_ST   = TI * 2048;            // bytes per A stage
    constexpr int C_OFF  = 3 * A_ST;             // codes: 3 x 8192 (128 rows x 64B)
    constexpr int AM_OFF = C_OFF + 3 * 8192;     // absmax: 3 x 512
    constexpr int LUT_OFF = AM_OFF + 1536;       // 512 floats

    extern __shared__ char smem[];
    const uint32_t sb = smem_u32(smem);

    const int tid = threadIdx.x;
    const int warp = tid >> 5, lane = tid & 31;
    const int warpT = warp >> 2, warpM = warp & 3;
    const int tg = lane >> 2, tig = lane & 3;
    const int t0 = blockIdx.y * (TI * 32);
    const int m0 = blockIdx.x * 128;
    const int t0g = t0 >> 4;
    const int kb = K >> 6;
    const int Kb16 = K >> 4;
    const int ktiles = K >> 5;

    {   // bank-replicated NF4 LUT
        float* Lut = (float*)(smem + LUT_OFF);
        for (int i = tid; i < 512; i += 256) Lut[i] = NF4c[i >> 5];
    }

    float acc[TI][4][4];
#pragma unroll
    for (int i = 0; i < TI; i++)
#pragma unroll
        for (int j = 0; j < 4; j++)
#pragma unroll
            for (int r = 0; r < 4; r++) acc[i][j][r] = 0.f;

    auto issue_load = [&](int kt) {
        const int s = kt % 3;
        const int k0 = kt * 32;
        const uint32_t aS = sb + s * A_ST;
#pragma unroll
        for (int i = 0; i < TI / 2; i++) {
            int idx = tid + i * 256;
            int tt = idx >> 6, kbi = (idx >> 5) & 1, ln = idx & 31;
            const __half* src = Ap + (((size_t)(t0g + tt) * Kb16 + (k0 >> 4) + kbi) * 32 + ln) * 8;
            cpa16(aS + (uint32_t)idx * 16, src);
        }
        {
            int row = tid >> 1, ch = tid & 1;
            int slot = (ch ^ (row & 3)) & 3;
            cpa16(sb + C_OFF + s * 8192 + row * 64 + slot * 16,
                  codes + (size_t)(m0 + row) * K + k0 + ch * 16);
        }
        if (tid < 128)
            cpa4(sb + AM_OFF + s * 512 + tid * 4,
                 absmax + (size_t)(m0 + tid) * kb + (k0 >> 6));
        asm volatile("cp.async.commit_group;" ::: "memory");
    };

    issue_load(0);
    issue_load(1);

    const float* Lut = (const float*)(smem + LUT_OFF);

    for (int kt = 0; kt < ktiles; kt++) {
        const int s = kt % 3;
        if (kt < ktiles - 1) asm volatile("cp.async.wait_group 1;" ::: "memory");
        else                 asm volatile("cp.async.wait_group 0;" ::: "memory");
        __syncthreads();

        const char* AsS = smem + s * A_ST;
        const char* CsS = smem + C_OFF + s * 8192;
        const float* AmS = (const float*)(smem + AM_OFF + s * 512);

        float am[4];
#pragma unroll
        for (int j = 0; j < 4; j++) am[j] = AmS[warpM * 32 + j * 8 + tg];

#pragma unroll
        for (int kc = 0; kc < 2; kc++) {
            uint32_t a[TI][4], b[4][2];
#pragma unroll
            for (int i = 0; i < TI; i++) {
                int tt = warpT * TI + i;
                uint4 v = *(const uint4*)(AsS + ((tt * 2 + kc) * 32 + lane) * 16);
                a[i][0] = v.x; a[i][1] = v.y; a[i][2] = v.z; a[i][3] = v.w;
            }
#pragma unroll
            for (int j = 0; j < 4; j++) {
                int mr = warpM * 32 + j * 8 + tg;
                int slot = (kc ^ (mr & 3)) & 3;
                uint4 q = *(const uint4*)(CsS + mr * 64 + slot * 16);
                uint32_t wlo = (tig < 2) ? q.x : q.y;
                uint32_t whi = (tig < 2) ? q.z : q.w;
                uint32_t sh = (tig & 1) * 16;
                uint32_t plo = (wlo >> sh) & 0xFFFFu;
                uint32_t phi = (whi >> sh) & 0xFFFFu;
                float f0 = Lut[((plo & 0xFFu) << 5) + lane] * am[j];
                float f1 = Lut[((plo >> 8) << 5) + lane] * am[j];
                float f2 = Lut[((phi & 0xFFu) << 5) + lane] * am[j];
                float f3 = Lut[((phi >> 8) << 5) + lane] * am[j];
                b[j][0] = f2h2(f0, f1);
                b[j][1] = f2h2(f2, f3);
            }
#pragma unroll
            for (int i = 0; i < TI; i++)
#pragma unroll
                for (int j = 0; j < 4; j++) {
                    asm volatile(
                        "mma.sync.aligned.m16n8k16.row.col.f32.f16.f16.f32 "
                        "{%0,%1,%2,%3}, {%4,%5,%6,%7}, {%8,%9}, {%0,%1,%2,%3};"
                        : "+f"(acc[i][j][0]), "+f"(acc[i][j][1]),
                          "+f"(acc[i][j][2]), "+f"(acc[i][j][3])
                        : "r"(a[i][0]), "r"(a[i][1]), "r"(a[i][2]), "r"(a[i][3]),
                          "r"(b[j][0]), "r"(b[j][1]));
                }
        }

        if (kt + 2 < ktiles) issue_load(kt + 2);
    }

    if (EPI == 1) {
        // h = silu(g) * acc -> fp16, staged to permuted layout via smem
        __syncthreads();
        uint32_t* Ep = (uint32_t*)smem;   // [8 t-blk][8 m-blk][32 lanes][4 words]
#pragma unroll
        for (int i = 0; i < TI; i++) {
#pragma unroll
            for (int j = 0; j < 4; j++) {
                int t = t0 + warpT * (TI * 16) + i * 16 + tg;
                int m = m0 + warpM * 32 + j * 8 + tig * 2;
                float2 glo = *(const float2*)&gbuf[(size_t)t * Mout + m];
                float2 ghi = *(const float2*)&gbuf[(size_t)(t + 8) * Mout + m];
                float h00 = glo.x / (1.f + __expf(-glo.x)) * acc[i][j][0];
                float h01 = glo.y / (1.f + __expf(-glo.y)) * acc[i][j][1];
                float h10 = ghi.x / (1.f + __expf(-ghi.x)) * acc[i][j][2];
                float h11 = ghi.y / (1.f + __expf(-ghi.y)) * acc[i][j][3];
                int tt = warpT * TI + i;
                int mb = warpM * 2 + (j >> 1);
                uint32_t* wptr = Ep + ((tt * 8 + mb) * 32 + lane) * 4 + (j & 1) * 2;
                wptr[0] = f2h2(h00, h01);
                wptr[1] = f2h2(h10, h11);
            }
        }
        __syncthreads();
        const int Mb16 = Mout >> 4;
        for (int idx = tid; idx < 2048; idx += 256) {
            int tt = idx >> 8, mb = (idx >> 5) & 7, ln = idx & 31;
            uint4 v = *(const uint4*)((const char*)Ep + idx * 16);
            size_t gb = (size_t)(t0g + tt) * Mb16 + (m0 >> 4) + mb;
            *(uint4*)(outh + (gb * 32 + ln) * 8) = v;
        }
    } else {
#pragma unroll
        for (int i = 0; i < TI; i++) {
#pragma unroll
            for (int j = 0; j < 4; j++) {
                int t = t0 + warpT * (TI * 16) + i * 16 + tg;
                int m = m0 + warpM * 32 + j * 8 + tig * 2;
                *(float2*)&outf[(size_t)t * Mout + m] = make_float2(acc[i][j][0], acc[i][j][1]);
                *(float2*)&outf[(size_t)(t + 8) * Mout + m] = make_float2(acc[i][j][2], acc[i][j][3]);
            }
        }
    }
}

extern "C" void kernel_launch(void* const* d_in, const int* in_sizes, int n_in,
                              void* d_out, int out_size) {
    (void)in_sizes; (void)n_in; (void)out_size;
    const float* x           = (const float*)d_in[0];
    const int*   gate_codes  = (const int*)d_in[1];
    const float* gate_absmax = (const float*)d_in[2];
    const int*   up_codes    = (const int*)d_in[3];
    const float* up_absmax   = (const float*)d_in[4];
    const int*   down_codes  = (const int*)d_in[5];
    const float* down_absmax = (const float*)d_in[6];
    float* out = (float*)d_out;

    unsigned char *cg, *cu, *cd;
    __half *xq, *hp;
    float *gg;
    cudaGetSymbolAddress((void**)&cg, g_codes_gate);
    cudaGetSymbolAddress((void**)&cu, g_codes_up);
    cudaGetSymbolAddress((void**)&cd, g_codes_down);
    cudaGetSymbolAddress((void**)&xq, g_xq);
    cudaGetSymbolAddress((void**)&gg, g_g);
    cudaGetSymbolAddress((void**)&hp, g_hp);

    const int SM4 = 3 * (4 * 2048) + 3 * 8192 + 1536 + 2048;  // 52736
    const int SM2 = 3 * (2 * 2048) + 3 * 8192 + 1536 + 2048;  // 40448
    cudaFuncSetAttribute((const void*)gemm_h<4, 0>, cudaFuncAttributeMaxDynamicSharedMemorySize, SM4);
    cudaFuncSetAttribute((const void*)gemm_h<4, 1>, cudaFuncAttributeMaxDynamicSharedMemorySize, SM4);
    cudaFuncSetAttribute((const void*)gemm_h<2, 0>, cudaFuncAttributeMaxDynamicSharedMemorySize, SM2);

    const int ncodes = MDIM * HD;
    const int n4 = ncodes / 4;
    pack_codes<<<(n4 + 255) / 256, 256>>>(gate_codes, cg, n4);
    pack_codes<<<(n4 + 255) / 256, 256>>>(up_codes, cu, n4);
    pack_codes<<<(n4 + 255) / 256, 256>>>(down_codes, cd, n4);

    {
        int nwarps = (TOK / 16) * (HD / 16);     // 8192
        int nthreads = nwarps * 32;
        permute_xh<<<(nthreads + 255) / 256, 256>>>(x, xq, TOK, HD);
    }

    dim3 grid1(MDIM / 128, TOK / 128);   // (86, 4)
    gemm_h<4, 0><<<grid1, 256, SM4>>>(xq, cg, gate_absmax, nullptr, gg, nullptr, HD, MDIM);
    gemm_h<4, 1><<<grid1, 256, SM4>>>(xq, cu, up_absmax, gg, nullptr, hp, HD, MDIM);

    dim3 grid2(HD / 128, TOK / 64);      // (32, 8)
    gemm_h<2, 0><<<grid2, 256, SM2>>>(hp, cd, down_absmax, nullptr, out, nullptr, MDIM, HD);
}

// round 5
// speedup vs baseline: 5.0031x; 1.4915x over previous
#include <cuda_runtime.h>
#include <cuda_fp16.h>
#include <cstdint>

// Problem dims (fixed by dataset)
#define HD    4096
#define MDIM  11008
#define TOK   512

__constant__ float NF4c[16] = {
    -1.0f, -0.6961928009986877f, -0.5250730514526367f, -0.39491748809814453f,
    -0.28444138169288635f, -0.18477343022823334f, -0.09105003625154495f, 0.0f,
    0.07958029955625534f, 0.16093020141124725f, 0.24611230194568634f,
    0.33791524171829224f, 0.44070982933044434f, 0.5626170039176941f,
    0.7229568362236023f, 1.0f};

// Static device scratch
__device__ __half g_wg[(size_t)MDIM * HD];   // gate W fp16, B-frag permuted
__device__ __half g_wu[(size_t)MDIM * HD];   // up   W fp16, B-frag permuted
__device__ __half g_wd[(size_t)HD * MDIM];   // down W fp16, B-frag permuted
__device__ __half g_xq[(size_t)TOK * HD];    // x fp16, A-frag permuted
__device__ float  g_g[(size_t)TOK * MDIM];   // gate GEMM out, linear fp32
__device__ __half g_hp[(size_t)TOK * MDIM];  // h fp16, A-frag permuted

__device__ __forceinline__ void cpa16(uint32_t dst, const void* src) {
    asm volatile("cp.async.cg.shared.global [%0], [%1], 16;" :: "r"(dst), "l"(src));
}
__device__ __forceinline__ uint32_t smem_u32(const void* p) {
    uint32_t a;
    asm("{ .reg .u64 t; cvta.to.shared.u64 t, %1; cvt.u32.u64 %0, t; }" : "=r"(a) : "l"(p));
    return a;
}
__device__ __forceinline__ uint32_t f2h2(float lo, float hi) {
    uint32_t r;
    asm("cvt.rn.f16x2.f32 %0, %2, %1;" : "=r"(r) : "f"(lo), "f"(hi));
    return r;
}

// ---------------- permute x -> fp16 A-fragment layout ----------------
// layout: [T/16][K/16][32 lanes][4 x f16x2]
__global__ void permute_xh(const float* __restrict__ X, __half* __restrict__ Xp, int T, int K) {
    int gw = (blockIdx.x * blockDim.x + threadIdx.x) >> 5;
    int lane = threadIdx.x & 31;
    int kb16 = K >> 4;
    if (gw >= (T >> 4) * kb16) return;
    int tb = gw / kb16, kb = gw % kb16;
    int tg = lane >> 2, tig = lane & 3;
    const float* p0 = X + (size_t)(tb * 16 + tg) * K + kb * 16 + tig * 2;
    const float* p1 = p0 + (size_t)8 * K;
    float2 v00 = *(const float2*)p0;
    float2 v10 = *(const float2*)p1;
    float2 v01 = *(const float2*)(p0 + 8);
    float2 v11 = *(const float2*)(p1 + 8);
    uint4 o;
    o.x = f2h2(v00.x, v00.y);
    o.y = f2h2(v10.x, v10.y);
    o.z = f2h2(v01.x, v01.y);
    o.w = f2h2(v11.x, v11.y);
    *(uint4*)(Xp + ((size_t)gw * 32 + lane) * 8) = o;
}

// ---------------- dequant NF4 int32 codes -> fp16 W in B-frag layout ----------------
// W layout: [M/8 nb][K/16 kb][32 lanes][2 x f16x2]; lane: n=lane>>2, tig=lane&3
// b0 = {W[n][tig*2], W[n][tig*2+1]}, b1 = {W[n][tig*2+8], W[n][tig*2+9]}
// One warp handles (nb, kb64): 8 rows x 64 k = one absmax block per row.
__global__ __launch_bounds__(256) void dequant_w(
    const int* __restrict__ codes, const float* __restrict__ absmax,
    __half* __restrict__ Wp, int M, int K)
{
    __shared__ float Lut[512];
    for (int i = threadIdx.x; i < 512; i += 256) Lut[i] = NF4c[i >> 5];
    __syncthreads();
    int gw = (blockIdx.x * 256 + threadIdx.x) >> 5;
    int lane = threadIdx.x & 31;
    int Kb64 = K >> 6, Kb16 = K >> 4;
    if (gw >= (M >> 3) * Kb64) return;
    int nb = gw / Kb64, kb64 = gw % Kb64;
    int n = lane >> 2, tig = lane & 3;
    int m = nb * 8 + n;
    float am = absmax[(size_t)m * Kb64 + kb64];
    const int* rp = codes + (size_t)m * K + (size_t)kb64 * 64;
#pragma unroll
    for (int q = 0; q < 4; q++) {
        int2 lo = *(const int2*)(rp + q * 16 + tig * 2);
        int2 hi = *(const int2*)(rp + q * 16 + tig * 2 + 8);
        uint2 o;
        o.x = f2h2(Lut[(lo.x << 5) + lane] * am, Lut[(lo.y << 5) + lane] * am);
        o.y = f2h2(Lut[(hi.x << 5) + lane] * am, Lut[(hi.y << 5) + lane] * am);
        *(uint2*)(Wp + ((size_t)nb * Kb16 + kb64 * 4 + q) * 128 + lane * 4) = o;
    }
}

// ---------------- pure fp16 HMMA GEMM ----------------
// out[T x Mout] = A[T x K] @ W^T, both operands pre-permuted fp16.
// BT = TI*32 tokens, BM = 128, BK = 32, 3-stage cp.async.
// EPI 0: linear fp32 store. EPI 1: h = silu(g)*acc -> fp16 permuted layout.
template<int TI, int EPI>
__global__ __launch_bounds__(256, 2) void gemm_f16(
    const __half* __restrict__ Ap,
    const __half* __restrict__ Wp,
    const float* __restrict__ gbuf,
    float* __restrict__ outf,
    __half* __restrict__ outh,
    int K, int Mout)
{
    constexpr int A_ST  = TI * 2048;          // bytes per A stage
    constexpr int B_OFF = 3 * A_ST;           // B: 3 x 8192

    extern __shared__ char smem[];
    const uint32_t sb = smem_u32(smem);

    const int tid = threadIdx.x;
    const int warp = tid >> 5, lane = tid & 31;
    const int warpT = warp >> 2, warpM = warp & 3;
    const int tg = lane >> 2, tig = lane & 3;
    const int t0 = blockIdx.y * (TI * 32);
    const int m0 = blockIdx.x * 128;
    const int t0g = t0 >> 4;
    const int m0g = m0 >> 3;
    const int Kb16 = K >> 4;
    const int ktiles = K >> 5;

    float acc[TI][4][4];
#pragma unroll
    for (int i = 0; i < TI; i++)
#pragma unroll
        for (int j = 0; j < 4; j++)
#pragma unroll
            for (int r = 0; r < 4; r++) acc[i][j][r] = 0.f;

    auto issue_load = [&](int kt) {
        const int s = kt % 3;
        const uint32_t aS = sb + s * A_ST;
#pragma unroll
        for (int i = 0; i < TI / 2; i++) {
            int idx = tid + i * 256;
            int tt = idx >> 6, kbi = (idx >> 5) & 1, ln = idx & 31;
            const __half* src = Ap + (((size_t)(t0g + tt) * Kb16 + kt * 2 + kbi) * 32 + ln) * 8;
            cpa16(aS + (uint32_t)idx * 16, src);
        }
        const uint32_t bS = sb + B_OFF + s * 8192;
#pragma unroll
        for (int i = 0; i < 2; i++) {
            int idx = tid + i * 256;
            int kbi = idx >> 8, nb = (idx >> 4) & 15, ln2 = idx & 15;
            const __half* src = Wp + ((size_t)(m0g + nb) * Kb16 + kt * 2 + kbi) * 128 + ln2 * 8;
            cpa16(bS + (uint32_t)idx * 16, src);
        }
        asm volatile("cp.async.commit_group;" ::: "memory");
    };

    issue_load(0);
    issue_load(1);

    for (int kt = 0; kt < ktiles; kt++) {
        const int s = kt % 3;
        if (kt < ktiles - 1) asm volatile("cp.async.wait_group 1;" ::: "memory");
        else                 asm volatile("cp.async.wait_group 0;" ::: "memory");
        __syncthreads();

        const char* AsS = smem + s * A_ST;
        const char* BsS = smem + B_OFF + s * 8192;

#pragma unroll
        for (int kc = 0; kc < 2; kc++) {
            uint32_t a[TI][4], b[4][2];
#pragma unroll
            for (int i = 0; i < TI; i++) {
                int tt = warpT * TI + i;
                uint4 v = *(const uint4*)(AsS + ((tt * 2 + kc) * 32 + lane) * 16);
                a[i][0] = v.x; a[i][1] = v.y; a[i][2] = v.z; a[i][3] = v.w;
            }
#pragma unroll
            for (int j = 0; j < 4; j++) {
                uint2 w = *(const uint2*)(BsS + ((kc * 16 + warpM * 4 + j) * 32 + lane) * 8);
                b[j][0] = w.x; b[j][1] = w.y;
            }
#pragma unroll
            for (int i = 0; i < TI; i++)
#pragma unroll
                for (int j = 0; j < 4; j++) {
                    asm volatile(
                        "mma.sync.aligned.m16n8k16.row.col.f32.f16.f16.f32 "
                        "{%0,%1,%2,%3}, {%4,%5,%6,%7}, {%8,%9}, {%0,%1,%2,%3};"
                        : "+f"(acc[i][j][0]), "+f"(acc[i][j][1]),
                          "+f"(acc[i][j][2]), "+f"(acc[i][j][3])
                        : "r"(a[i][0]), "r"(a[i][1]), "r"(a[i][2]), "r"(a[i][3]),
                          "r"(b[j][0]), "r"(b[j][1]));
                }
        }

        if (kt + 2 < ktiles) issue_load(kt + 2);
    }

    if (EPI == 1) {
        // h = silu(g) * acc -> fp16, staged to permuted layout via smem
        __syncthreads();
        uint32_t* Ep = (uint32_t*)smem;   // [8 t-blk][8 m-blk][32 lanes][4 words]
#pragma unroll
        for (int i = 0; i < TI; i++) {
#pragma unroll
            for (int j = 0; j < 4; j++) {
                int t = t0 + warpT * (TI * 16) + i * 16 + tg;
                int m = m0 + warpM * 32 + j * 8 + tig * 2;
                float2 glo = *(const float2*)&gbuf[(size_t)t * Mout + m];
                float2 ghi = *(const float2*)&gbuf[(size_t)(t + 8) * Mout + m];
                float h00 = glo.x / (1.f + __expf(-glo.x)) * acc[i][j][0];
                float h01 = glo.y / (1.f + __expf(-glo.y)) * acc[i][j][1];
                float h10 = ghi.x / (1.f + __expf(-ghi.x)) * acc[i][j][2];
                float h11 = ghi.y / (1.f + __expf(-ghi.y)) * acc[i][j][3];
                int tt = warpT * TI + i;
                int mb = warpM * 2 + (j >> 1);
                uint32_t* wptr = Ep + ((tt * 8 + mb) * 32 + lane) * 4 + (j & 1) * 2;
                wptr[0] = f2h2(h00, h01);
                wptr[1] = f2h2(h10, h11);
            }
        }
        __syncthreads();
        const int Mb16 = Mout >> 4;
        for (int idx = tid; idx < 2048; idx += 256) {
            int tt = idx >> 8, mb = (idx >> 5) & 7, ln = idx & 31;
            uint4 v = *(const uint4*)((const char*)Ep + idx * 16);
            size_t gb = (size_t)(t0g + tt) * Mb16 + (m0 >> 4) + mb;
            *(uint4*)(outh + (gb * 32 + ln) * 8) = v;
        }
    } else {
#pragma unroll
        for (int i = 0; i < TI; i++) {
#pragma unroll
            for (int j = 0; j < 4; j++) {
                int t = t0 + warpT * (TI * 16) + i * 16 + tg;
                int m = m0 + warpM * 32 + j * 8 + tig * 2;
                *(float2*)&outf[(size_t)t * Mout + m] = make_float2(acc[i][j][0], acc[i][j][1]);
                *(float2*)&outf[(size_t)(t + 8) * Mout + m] = make_float2(acc[i][j][2], acc[i][j][3]);
            }
        }
    }
}

extern "C" void kernel_launch(void* const* d_in, const int* in_sizes, int n_in,
                              void* d_out, int out_size) {
    (void)in_sizes; (void)n_in; (void)out_size;
    const float* x           = (const float*)d_in[0];
    const int*   gate_codes  = (const int*)d_in[1];
    const float* gate_absmax = (const float*)d_in[2];
    const int*   up_codes    = (const int*)d_in[3];
    const float* up_absmax   = (const float*)d_in[4];
    const int*   down_codes  = (const int*)d_in[5];
    const float* down_absmax = (const float*)d_in[6];
    float* out = (float*)d_out;

    __half *wg, *wu, *wd, *xq, *hp;
    float *gg;
    cudaGetSymbolAddress((void**)&wg, g_wg);
    cudaGetSymbolAddress((void**)&wu, g_wu);
    cudaGetSymbolAddress((void**)&wd, g_wd);
    cudaGetSymbolAddress((void**)&xq, g_xq);
    cudaGetSymbolAddress((void**)&gg, g_g);
    cudaGetSymbolAddress((void**)&hp, g_hp);

    const int SM4 = 3 * (4 * 2048) + 3 * 8192 + 1024;  // 49152+..
    const int SM2 = 3 * (2 * 2048) + 3 * 8192 + 1024;
    cudaFuncSetAttribute((const void*)gemm_f16<4, 0>, cudaFuncAttributeMaxDynamicSharedMemorySize, SM4);
    cudaFuncSetAttribute((const void*)gemm_f16<4, 1>, cudaFuncAttributeMaxDynamicSharedMemorySize, SM4);
    cudaFuncSetAttribute((const void*)gemm_f16<2, 0>, cudaFuncAttributeMaxDynamicSharedMemorySize, SM2);

    {
        int nwarps = (TOK / 16) * (HD / 16);
        permute_xh<<<(nwarps * 32 + 255) / 256, 256>>>(x, xq, TOK, HD);
    }
    {
        int nblk1 = ((MDIM / 8) * (HD / 64) * 32 + 255) / 256;   // 11008
        int nblk2 = ((HD / 8) * (MDIM / 64) * 32 + 255) / 256;   // 11008
        dequant_w<<<nblk1, 256>>>(gate_codes, gate_absmax, wg, MDIM, HD);
        dequant_w<<<nblk1, 256>>>(up_codes, up_absmax, wu, MDIM, HD);
        dequant_w<<<nblk2, 256>>>(down_codes, down_absmax, wd, HD, MDIM);
    }

    dim3 grid1(MDIM / 128, TOK / 128);   // (86, 4)
    gemm_f16<4, 0><<<grid1, 256, SM4>>>(xq, wg, nullptr, gg, nullptr, HD, MDIM);
    gemm_f16<4, 1><<<grid1, 256, SM4>>>(xq, wu, gg, nullptr, hp, HD, MDIM);

    dim3 grid2(HD / 128, TOK / 64);      // (32, 8)
    gemm_f16<2, 0><<<grid2, 256, SM2>>>(hp, wd, nullptr, out, nullptr, MDIM, HD);
}

// round 6
// speedup vs baseline: 5.6875x; 1.1368x over previous
#include <cuda_runtime.h>
#include <cuda_fp16.h>
#include <cstdint>

// Problem dims (fixed by dataset)
#define HD    4096
#define MDIM  11008
#define TOK   512

__constant__ float NF4c[16] = {
    -1.0f, -0.6961928009986877f, -0.5250730514526367f, -0.39491748809814453f,
    -0.28444138169288635f, -0.18477343022823334f, -0.09105003625154495f, 0.0f,
    0.07958029955625534f, 0.16093020141124725f, 0.24611230194568634f,
    0.33791524171829224f, 0.44070982933044434f, 0.5626170039176941f,
    0.7229568362236023f, 1.0f};

// Static device scratch
__device__ __half g_wg[(size_t)MDIM * HD];   // gate W fp16, B-frag permuted
__device__ __half g_wu[(size_t)MDIM * HD];   // up   W fp16, B-frag permuted
__device__ __half g_wd[(size_t)HD * MDIM];   // down W fp16, B-frag permuted
__device__ __half g_xq[(size_t)TOK * HD];    // x fp16, A-frag permuted
__device__ __half g_hp[(size_t)TOK * MDIM];  // h fp16, A-frag permuted

__device__ __forceinline__ void cpa16(uint32_t dst, const void* src) {
    asm volatile("cp.async.cg.shared.global [%0], [%1], 16;" :: "r"(dst), "l"(src));
}
__device__ __forceinline__ uint32_t smem_u32(const void* p) {
    uint32_t a;
    asm("{ .reg .u64 t; cvta.to.shared.u64 t, %1; cvt.u32.u64 %0, t; }" : "=r"(a) : "l"(p));
    return a;
}
__device__ __forceinline__ uint32_t f2h2(float lo, float hi) {
    uint32_t r;
    asm("cvt.rn.f16x2.f32 %0, %2, %1;" : "=r"(r) : "f"(lo), "f"(hi));
    return r;
}
#define MMA_H(acc, a, b0, b1) \
    asm volatile( \
        "mma.sync.aligned.m16n8k16.row.col.f32.f16.f16.f32 " \
        "{%0,%1,%2,%3}, {%4,%5,%6,%7}, {%8,%9}, {%0,%1,%2,%3};" \
        : "+f"(acc[0]), "+f"(acc[1]), "+f"(acc[2]), "+f"(acc[3]) \
        : "r"(a[0]), "r"(a[1]), "r"(a[2]), "r"(a[3]), "r"(b0), "r"(b1))

// ---------------- permute x -> fp16 A-fragment layout ----------------
// layout: [T/16][K/16][32 lanes][4 x f16x2]
__global__ void permute_xh(const float* __restrict__ X, __half* __restrict__ Xp, int T, int K) {
    int gw = (blockIdx.x * blockDim.x + threadIdx.x) >> 5;
    int lane = threadIdx.x & 31;
    int kb16 = K >> 4;
    if (gw >= (T >> 4) * kb16) return;
    int tb = gw / kb16, kb = gw % kb16;
    int tg = lane >> 2, tig = lane & 3;
    const float* p0 = X + (size_t)(tb * 16 + tg) * K + kb * 16 + tig * 2;
    const float* p1 = p0 + (size_t)8 * K;
    float2 v00 = *(const float2*)p0;
    float2 v10 = *(const float2*)p1;
    float2 v01 = *(const float2*)(p0 + 8);
    float2 v11 = *(const float2*)(p1 + 8);
    uint4 o;
    o.x = f2h2(v00.x, v00.y);
    o.y = f2h2(v10.x, v10.y);
    o.z = f2h2(v01.x, v01.y);
    o.w = f2h2(v11.x, v11.y);
    *(uint4*)(Xp + ((size_t)gw * 32 + lane) * 8) = o;
}

// ---------------- dequant NF4 int32 codes -> fp16 W in B-frag layout ----------------
__global__ __launch_bounds__(256) void dequant_w(
    const int* __restrict__ codes, const float* __restrict__ absmax,
    __half* __restrict__ Wp, int M, int K)
{
    __shared__ float Lut[512];
    for (int i = threadIdx.x; i < 512; i += 256) Lut[i] = NF4c[i >> 5];
    __syncthreads();
    int gw = (blockIdx.x * 256 + threadIdx.x) >> 5;
    int lane = threadIdx.x & 31;
    int Kb64 = K >> 6, Kb16 = K >> 4;
    if (gw >= (M >> 3) * Kb64) return;
    int nb = gw / Kb64, kb64 = gw % Kb64;
    int n = lane >> 2, tig = lane & 3;
    int m = nb * 8 + n;
    float am = absmax[(size_t)m * Kb64 + kb64];
    const int* rp = codes + (size_t)m * K + (size_t)kb64 * 64;
#pragma unroll
    for (int q = 0; q < 4; q++) {
        int2 lo = *(const int2*)(rp + q * 16 + tig * 2);
        int2 hi = *(const int2*)(rp + q * 16 + tig * 2 + 8);
        uint2 o;
        o.x = f2h2(Lut[(lo.x << 5) + lane] * am, Lut[(lo.y << 5) + lane] * am);
        o.y = f2h2(Lut[(hi.x << 5) + lane] * am, Lut[(hi.y << 5) + lane] * am);
        *(uint2*)(Wp + ((size_t)nb * Kb16 + kb64 * 4 + q) * 128 + lane * 4) = o;
    }
}

// ---------------- fused gate+up GEMM + silu ----------------
// BT=64, BM=128: acc_g = x@Wg^T, acc_u = x@Wu^T, out hp = silu(g)*u (fp16 permuted)
__global__ __launch_bounds__(256, 2) void gemm_gateup(
    const __half* __restrict__ Ap,
    const __half* __restrict__ Wg,
    const __half* __restrict__ Wu,
    __half* __restrict__ outh,
    int K, int Mout)
{
    constexpr int A_ST = 4096;                 // 64 tok x 32 k fp16
    constexpr int BG_OFF = 3 * A_ST;           // gate B: 3 x 8192
    constexpr int BU_OFF = BG_OFF + 3 * 8192;  // up   B: 3 x 8192

    extern __shared__ char smem[];
    const uint32_t sb = smem_u32(smem);

    const int tid = threadIdx.x;
    const int warp = tid >> 5, lane = tid & 31;
    const int warpT = warp >> 2, warpM = warp & 3;
    const int tg = lane >> 2, tig = lane & 3;
    const int t0g = blockIdx.y * 4;            // 64 tokens = 4 blocks of 16
    const int m0 = blockIdx.x * 128;
    const int m0g = m0 >> 3;
    const int Kb16 = K >> 4;
    const int ktiles = K >> 5;

    float ag[2][4][4], au[2][4][4];
#pragma unroll
    for (int i = 0; i < 2; i++)
#pragma unroll
        for (int j = 0; j < 4; j++)
#pragma unroll
            for (int r = 0; r < 4; r++) { ag[i][j][r] = 0.f; au[i][j][r] = 0.f; }

    auto issue_load = [&](int kt) {
        const int s = kt % 3;
        {
            int tt = tid >> 6, kbi = (tid >> 5) & 1, ln = tid & 31;
            const __half* src = Ap + (((size_t)(t0g + tt) * Kb16 + kt * 2 + kbi) * 32 + ln) * 8;
            cpa16(sb + s * A_ST + (uint32_t)tid * 16, src);
        }
#pragma unroll
        for (int i = 0; i < 2; i++) {
            int idx = tid + i * 256;
            int kbi = idx >> 8, nb = (idx >> 4) & 15, ln2 = idx & 15;
            size_t off = ((size_t)(m0g + nb) * Kb16 + kt * 2 + kbi) * 128 + ln2 * 8;
            cpa16(sb + BG_OFF + s * 8192 + (uint32_t)idx * 16, Wg + off);
            cpa16(sb + BU_OFF + s * 8192 + (uint32_t)idx * 16, Wu + off);
        }
        asm volatile("cp.async.commit_group;" ::: "memory");
    };

    issue_load(0);
    issue_load(1);

    for (int kt = 0; kt < ktiles; kt++) {
        const int s = kt % 3;
        if (kt < ktiles - 1) asm volatile("cp.async.wait_group 1;" ::: "memory");
        else                 asm volatile("cp.async.wait_group 0;" ::: "memory");
        __syncthreads();

        const char* AsS = smem + s * A_ST;
        const char* BgS = smem + BG_OFF + s * 8192;
        const char* BuS = smem + BU_OFF + s * 8192;

#pragma unroll
        for (int kc = 0; kc < 2; kc++) {
            uint32_t a[2][4], bg[4][2], bu[4][2];
#pragma unroll
            for (int i = 0; i < 2; i++) {
                int tt = warpT * 2 + i;
                uint4 v = *(const uint4*)(AsS + ((tt * 2 + kc) * 32 + lane) * 16);
                a[i][0] = v.x; a[i][1] = v.y; a[i][2] = v.z; a[i][3] = v.w;
            }
#pragma unroll
            for (int j = 0; j < 4; j++) {
                int row = (kc * 16 + warpM * 4 + j) * 32 + lane;
                uint2 wg2 = *(const uint2*)(BgS + row * 8);
                uint2 wu2 = *(const uint2*)(BuS + row * 8);
                bg[j][0] = wg2.x; bg[j][1] = wg2.y;
                bu[j][0] = wu2.x; bu[j][1] = wu2.y;
            }
#pragma unroll
            for (int i = 0; i < 2; i++)
#pragma unroll
                for (int j = 0; j < 4; j++) {
                    MMA_H(ag[i][j], a[i], bg[j][0], bg[j][1]);
                    MMA_H(au[i][j], a[i], bu[j][0], bu[j][1]);
                }
        }

        if (kt + 2 < ktiles) issue_load(kt + 2);
    }

    // epilogue: h = silu(g)*u -> fp16, staged to permuted layout via smem
    __syncthreads();
    uint32_t* Ep = (uint32_t*)smem;   // [4 t-blk][8 m-blk][32 lanes][4 words] = 16KB
#pragma unroll
    for (int i = 0; i < 2; i++) {
#pragma unroll
        for (int j = 0; j < 4; j++) {
            float h0 = ag[i][j][0] / (1.f + __expf(-ag[i][j][0])) * au[i][j][0];
            float h1 = ag[i][j][1] / (1.f + __expf(-ag[i][j][1])) * au[i][j][1];
            float h2 = ag[i][j][2] / (1.f + __expf(-ag[i][j][2])) * au[i][j][2];
            float h3 = ag[i][j][3] / (1.f + __expf(-ag[i][j][3])) * au[i][j][3];
            int tt = warpT * 2 + i;
            int mb = warpM * 2 + (j >> 1);
            uint32_t* wptr = Ep + ((tt * 8 + mb) * 32 + lane) * 4 + (j & 1) * 2;
            wptr[0] = f2h2(h0, h1);
            wptr[1] = f2h2(h2, h3);
        }
    }
    __syncthreads();
    const int Mb16 = Mout >> 4;
    for (int idx = tid; idx < 1024; idx += 256) {
        int tt = idx >> 8, mb = (idx >> 5) & 7, ln = idx & 31;
        uint4 v = *(const uint4*)((const char*)Ep + idx * 16);
        size_t gb = (size_t)(t0g + tt) * Mb16 + (m0 >> 4) + mb;
        *(uint4*)(outh + (gb * 32 + ln) * 8) = v;
    }
}

// ---------------- pure fp16 HMMA GEMM (down projection) ----------------
// BT=64 (TI=2), BM=128, linear fp32 store.
__global__ __launch_bounds__(256, 2) void gemm_down(
    const __half* __restrict__ Ap,
    const __half* __restrict__ Wp,
    float* __restrict__ outf,
    int K, int Mout)
{
    constexpr int A_ST  = 4096;
    constexpr int B_OFF = 3 * A_ST;

    extern __shared__ char smem[];
    const uint32_t sb = smem_u32(smem);

    const int tid = threadIdx.x;
    const int warp = tid >> 5, lane = tid & 31;
    const int warpT = warp >> 2, warpM = warp & 3;
    const int tg = lane >> 2, tig = lane & 3;
    const int t0 = blockIdx.y * 64;
    const int m0 = blockIdx.x * 128;
    const int t0g = t0 >> 4;
    const int m0g = m0 >> 3;
    const int Kb16 = K >> 4;
    const int ktiles = K >> 5;

    float acc[2][4][4];
#pragma unroll
    for (int i = 0; i < 2; i++)
#pragma unroll
        for (int j = 0; j < 4; j++)
#pragma unroll
            for (int r = 0; r < 4; r++) acc[i][j][r] = 0.f;

    auto issue_load = [&](int kt) {
        const int s = kt % 3;
        {
            int tt = tid >> 6, kbi = (tid >> 5) & 1, ln = tid & 31;
            const __half* src = Ap + (((size_t)(t0g + tt) * Kb16 + kt * 2 + kbi) * 32 + ln) * 8;
            cpa16(sb + s * A_ST + (uint32_t)tid * 16, src);
        }
#pragma unroll
        for (int i = 0; i < 2; i++) {
            int idx = tid + i * 256;
            int kbi = idx >> 8, nb = (idx >> 4) & 15, ln2 = idx & 15;
            const __half* src = Wp + ((size_t)(m0g + nb) * Kb16 + kt * 2 + kbi) * 128 + ln2 * 8;
            cpa16(sb + B_OFF + s * 8192 + (uint32_t)idx * 16, src);
        }
        asm volatile("cp.async.commit_group;" ::: "memory");
    };

    issue_load(0);
    issue_load(1);

    for (int kt = 0; kt < ktiles; kt++) {
        const int s = kt % 3;
        if (kt < ktiles - 1) asm volatile("cp.async.wait_group 1;" ::: "memory");
        else                 asm volatile("cp.async.wait_group 0;" ::: "memory");
        __syncthreads();

        const char* AsS = smem + s * A_ST;
        const char* BsS = smem + B_OFF + s * 8192;

#pragma unroll
        for (int kc = 0; kc < 2; kc++) {
            uint32_t a[2][4], b[4][2];
#pragma unroll
            for (int i = 0; i < 2; i++) {
                int tt = warpT * 2 + i;
                uint4 v = *(const uint4*)(AsS + ((tt * 2 + kc) * 32 + lane) * 16);
                a[i][0] = v.x; a[i][1] = v.y; a[i][2] = v.z; a[i][3] = v.w;
            }
#pragma unroll
            for (int j = 0; j < 4; j++) {
                uint2 w = *(const uint2*)(BsS + ((kc * 16 + warpM * 4 + j) * 32 + lane) * 8);
                b[j][0] = w.x; b[j][1] = w.y;
            }
#pragma unroll
            for (int i = 0; i < 2; i++)
#pragma unroll
                for (int j = 0; j < 4; j++)
                    MMA_H(acc[i][j], a[i], b[j][0], b[j][1]);
        }

        if (kt + 2 < ktiles) issue_load(kt + 2);
    }

#pragma unroll
    for (int i = 0; i < 2; i++) {
#pragma unroll
        for (int j = 0; j < 4; j++) {
            int t = t0 + warpT * 32 + i * 16 + tg;
            int m = m0 + warpM * 32 + j * 8 + tig * 2;
            *(float2*)&outf[(size_t)t * Mout + m] = make_float2(acc[i][j][0], acc[i][j][1]);
            *(float2*)&outf[(size_t)(t + 8) * Mout + m] = make_float2(acc[i][j][2], acc[i][j][3]);
        }
    }
}

extern "C" void kernel_launch(void* const* d_in, const int* in_sizes, int n_in,
                              void* d_out, int out_size) {
    (void)in_sizes; (void)n_in; (void)out_size;
    const float* x           = (const float*)d_in[0];
    const int*   gate_codes  = (const int*)d_in[1];
    const float* gate_absmax = (const float*)d_in[2];
    const int*   up_codes    = (const int*)d_in[3];
    const float* up_absmax   = (const float*)d_in[4];
    const int*   down_codes  = (const int*)d_in[5];
    const float* down_absmax = (const float*)d_in[6];
    float* out = (float*)d_out;

    __half *wg, *wu, *wd, *xq, *hp;
    cudaGetSymbolAddress((void**)&wg, g_wg);
    cudaGetSymbolAddress((void**)&wu, g_wu);
    cudaGetSymbolAddress((void**)&wd, g_wd);
    cudaGetSymbolAddress((void**)&xq, g_xq);
    cudaGetSymbolAddress((void**)&hp, g_hp);

    const int SM_GU = 3 * 4096 + 6 * 8192 + 1024;  // 62464
    const int SM_DN = 3 * 4096 + 3 * 8192 + 1024;  // 37888
    cudaFuncSetAttribute((const void*)gemm_gateup, cudaFuncAttributeMaxDynamicSharedMemorySize, SM_GU);
    cudaFuncSetAttribute((const void*)gemm_down, cudaFuncAttributeMaxDynamicSharedMemorySize, SM_DN);

    {
        int nwarps = (TOK / 16) * (HD / 16);
        permute_xh<<<(nwarps * 32 + 255) / 256, 256>>>(x, xq, TOK, HD);
    }
    {
        int nblk1 = ((MDIM / 8) * (HD / 64) * 32 + 255) / 256;
        int nblk2 = ((HD / 8) * (MDIM / 64) * 32 + 255) / 256;
        dequant_w<<<nblk1, 256>>>(gate_codes, gate_absmax, wg, MDIM, HD);
        dequant_w<<<nblk1, 256>>>(up_codes, up_absmax, wu, MDIM, HD);
        dequant_w<<<nblk2, 256>>>(down_codes, down_absmax, wd, HD, MDIM);
    }

    dim3 grid1(MDIM / 128, TOK / 64);    // (86, 8) = 688
    gemm_gateup<<<grid1, 256, SM_GU>>>(xq, wg, wu, hp, HD, MDIM);

    dim3 grid2(HD / 128, TOK / 64);      // (32, 8) = 256
    gemm_down<<<grid2, 256, SM_DN>>>(hp, wd, out, MDIM, HD);
}